// round 6
// baseline (speedup 1.0000x reference)
#include <cuda_runtime.h>
#include <cuda_bf16.h>
#include <cstdint>

#define BDIM   64
#define IOD    8192
#define OTILE  256
#define KSPLIT 8
#define KQ     (IOD / KSPLIT)     // 1024
#define KC     32                 // k elems per stage
#define NITER  (KQ / KC)          // 32
#define NSTAGE 3
#define STG_BYTES (OTILE * 128)   // 32768 (256 rows x 32 fp32)
#define SMEM_TOTAL (NSTAGE * STG_BYTES)   // 98304

// scratch (no cudaMalloc allowed)
// x pre-split hi/lo bf16, stored in mma m16n8k16 A-fragment order:
// uint4 index = (ks16 * 4 + mt) * 32 + lane
__device__ uint4 g_xfhi[(IOD / 16) * 4 * 32];   // 1 MB
__device__ uint4 g_xflo[(IOD / 16) * 4 * 32];   // 1 MB
__device__ float g_part[KSPLIT][BDIM * IOD];    // split-K partials (alpha applied)

// ---------------- helpers ----------------
__device__ __forceinline__ uint32_t swz(uint32_t off) {      // SW128 Swizzle<3,4,3>
    return off ^ ((off >> 3) & 0x70);
}

__device__ __forceinline__ void cp_async16(uint32_t dst, const void* src) {
    asm volatile("cp.async.cg.shared.global [%0], [%1], 16;" :: "r"(dst), "l"(src));
}
#define CP_COMMIT() asm volatile("cp.async.commit_group;" ::: "memory")
#define CP_WAIT2()  asm volatile("cp.async.wait_group 2;"  ::: "memory")
#define CP_WAIT1()  asm volatile("cp.async.wait_group 1;"  ::: "memory")
#define CP_WAIT0()  asm volatile("cp.async.wait_group 0;"  ::: "memory")

__device__ __forceinline__ void mma_bf16(float* c, const uint4& a,
                                         uint32_t b0, uint32_t b1) {
    asm volatile("mma.sync.aligned.m16n8k16.row.col.f32.bf16.bf16.f32 "
                 "{%0,%1,%2,%3}, {%4,%5,%6,%7}, {%8,%9}, {%0,%1,%2,%3};"
                 : "+f"(c[0]), "+f"(c[1]), "+f"(c[2]), "+f"(c[3])
                 : "r"(a.x), "r"(a.y), "r"(a.z), "r"(a.w), "r"(b0), "r"(b1));
}

__device__ __forceinline__ float2 lds_f2(uint32_t addr) {
    float2 v;
    asm volatile("ld.shared.v2.f32 {%0,%1}, [%2];" : "=f"(v.x), "=f"(v.y) : "r"(addr));
    return v;
}

// quantize 2 consecutive fp32 weights -> packed bf16x2 ternary {-1,0,+1}
__device__ __forceinline__ uint32_t qpair(float2 v, float thr) {
    uint32_t u0 = __float_as_uint(v.x), u1 = __float_as_uint(v.y);
    uint32_t r = 0;
    if (fabsf(v.x) > thr) r  = 0x3F80u     | ((u0 >> 16) & 0x8000u);
    if (fabsf(v.y) > thr) r |= 0x3F800000u | (u1 & 0x80000000u);
    return r;
}

__device__ __forceinline__ void hilo(float2 v, uint32_t& hi, uint32_t& lo) {
    __nv_bfloat16 hx = __float2bfloat16(v.x);
    __nv_bfloat16 hy = __float2bfloat16(v.y);
    __nv_bfloat162 h2, l2;
    h2.x = hx; h2.y = hy;
    l2.x = __float2bfloat16(v.x - __bfloat162float(hx));
    l2.y = __float2bfloat16(v.y - __bfloat162float(hy));
    hi = *reinterpret_cast<uint32_t*>(&h2);
    lo = *reinterpret_cast<uint32_t*>(&l2);
}

// ---------------- prep: x -> hi/lo bf16 in A-fragment layout ----------------
__global__ void prep_x(const float* __restrict__ x) {
    int t = blockIdx.x * blockDim.x + threadIdx.x;   // one thread per (ks, mt, lane)
    if (t >= (IOD / 16) * 4 * 32) return;
    int lane = t & 31;
    int mt   = (t >> 5) & 3;
    int ks   = t >> 7;
    int b0 = mt * 16 + (lane >> 2);
    int k0 = ks * 16 + (lane & 3) * 2;
    const float* p = x + (size_t)b0 * IOD + k0;
    float2 v00 = *reinterpret_cast<const float2*>(p);                 // (r,   c)
    float2 v10 = *reinterpret_cast<const float2*>(p + 8 * IOD);       // (r+8, c)
    float2 v01 = *reinterpret_cast<const float2*>(p + 8);             // (r,   c+8)
    float2 v11 = *reinterpret_cast<const float2*>(p + 8 * IOD + 8);   // (r+8, c+8)
    uint4 hi, lo;
    hilo(v00, hi.x, lo.x);
    hilo(v10, hi.y, lo.y);
    hilo(v01, hi.z, lo.z);
    hilo(v11, hi.w, lo.w);
    g_xfhi[t] = hi;
    g_xflo[t] = lo;
}

// ---------------- main GEMM ----------------
__global__ __launch_bounds__(256, 2) void qlin(
    const float* __restrict__ wgt,
    const float* __restrict__ alpha)
{
    extern __shared__ __align__(1024) unsigned char smem[];
    const uint32_t sb = (uint32_t)__cvta_generic_to_shared(smem);

    const int otile = blockIdx.x & 31;
    const int kq    = blockIdx.x >> 5;
    const int n0    = otile * OTILE;
    const int k0    = kq * KQ;

    const int tid  = threadIdx.x;
    const int lane = tid & 31;
    const int warp = tid >> 5;

    // cp.async mapping: thread handles 8 rows (crow + 32i), 16B slice (ccol) each
    const int crow = tid >> 3;
    const int ccol = (tid & 7) * 16;
    const float* wsrc = wgt + (size_t)(n0 + crow) * IOD + k0 + (tid & 7) * 4;

    // this warp's n-range and per-thread thresholds (one n8-row per nt)
    const int nb = warp * 32;                       // local n base (0..224)
    float thr[4];
#pragma unroll
    for (int nt = 0; nt < 4; ++nt)
        thr[nt] = 0.5f * (alpha[n0 + nb + nt * 8 + (lane >> 2)] + 1e-8f);

    float acc[4][4][4];
#pragma unroll
    for (int i = 0; i < 4; ++i)
#pragma unroll
        for (int j = 0; j < 4; ++j)
#pragma unroll
            for (int k = 0; k < 4; ++k) acc[i][j][k] = 0.0f;

    // prologue: stages 0,1 in flight
#pragma unroll
    for (int c = 0; c < 2; ++c) {
        uint32_t dst = sb + c * STG_BYTES;
        const float* src = wsrc + c * KC;
#pragma unroll
        for (int i = 0; i < 8; ++i)
            cp_async16(dst + swz((uint32_t)((crow + 32 * i) * 128 + ccol)),
                       src + (size_t)(32 * i) * IOD);
        CP_COMMIT();
    }

    for (int it = 0; it < NITER; ++it) {
        if (it + 2 < NITER) {
            uint32_t dst = sb + ((it + 2) % NSTAGE) * STG_BYTES;
            const float* src = wsrc + (it + 2) * KC;
#pragma unroll
            for (int i = 0; i < 8; ++i)
                cp_async16(dst + swz((uint32_t)((crow + 32 * i) * 128 + ccol)),
                           src + (size_t)(32 * i) * IOD);
            CP_COMMIT();
            CP_WAIT2();
        } else if (it + 1 < NITER) {
            CP_WAIT1();
        } else {
            CP_WAIT0();
        }
        __syncthreads();

        const uint32_t stg = sb + (it % NSTAGE) * STG_BYTES;

#pragma unroll
        for (int h = 0; h < 2; ++h) {               // two k16 steps per stage
            // B fragments: LDS fp32 pairs + quantize
            uint32_t b0[4], b1[4];
#pragma unroll
            for (int nt = 0; nt < 4; ++nt) {
                uint32_t base = (uint32_t)((nb + nt * 8 + (lane >> 2)) * 128
                                           + h * 64 + (lane & 3) * 8);
                float2 p0 = lds_f2(stg + swz(base));        // k = c, c+1
                float2 p1 = lds_f2(stg + swz(base + 32));   // k = c+8, c+9
                b0[nt] = qpair(p0, thr[nt]);
                b1[nt] = qpair(p1, thr[nt]);
            }
            const int ksg = kq * (KQ / 16) + it * 2 + h;    // global k16 index
#pragma unroll
            for (int mt = 0; mt < 4; ++mt) {
                uint4 ah = g_xfhi[(ksg * 4 + mt) * 32 + lane];
#pragma unroll
                for (int nt = 0; nt < 4; ++nt)
                    mma_bf16(acc[mt][nt], ah, b0[nt], b1[nt]);
                uint4 al = g_xflo[(ksg * 4 + mt) * 32 + lane];
#pragma unroll
                for (int nt = 0; nt < 4; ++nt)
                    mma_bf16(acc[mt][nt], al, b0[nt], b1[nt]);
            }
        }
        __syncthreads();
    }

    // epilogue: partial[b,o] = alpha[o] * acc   (bias added in reduce)
    float* part = g_part[kq];
#pragma unroll
    for (int mt = 0; mt < 4; ++mt) {
#pragma unroll
        for (int nt = 0; nt < 4; ++nt) {
            int b = mt * 16 + (lane >> 2);
            int o = n0 + nb + nt * 8 + (lane & 3) * 2;
            float2 a2 = *reinterpret_cast<const float2*>(alpha + o);
            float2 v0, v1;
            v0.x = acc[mt][nt][0] * a2.x;
            v0.y = acc[mt][nt][1] * a2.y;
            v1.x = acc[mt][nt][2] * a2.x;
            v1.y = acc[mt][nt][3] * a2.y;
            *reinterpret_cast<float2*>(part + (size_t)b * IOD + o)       = v0;
            *reinterpret_cast<float2*>(part + (size_t)(b + 8) * IOD + o) = v1;
        }
    }
}

// ---------------- reduce split-K partials + bias ----------------
__global__ void reduce_k(const float* __restrict__ bias, float* __restrict__ out) {
    int i = blockIdx.x * blockDim.x + threadIdx.x;     // float4 index
    if (i < (BDIM * IOD) / 4) {
        int o = (i * 4) & (IOD - 1);
        float4 b = *reinterpret_cast<const float4*>(bias + o);
        float4 r = b;
#pragma unroll
        for (int j = 0; j < KSPLIT; ++j) {
            float4 p = reinterpret_cast<const float4*>(g_part[j])[i];
            r.x += p.x; r.y += p.y; r.z += p.z; r.w += p.w;
        }
        reinterpret_cast<float4*>(out)[i] = r;
    }
}

extern "C" void kernel_launch(void* const* d_in, const int* in_sizes, int n_in,
                              void* d_out, int out_size) {
    const float* x     = (const float*)d_in[0];
    const float* wgt   = (const float*)d_in[1];
    const float* alpha = (const float*)d_in[2];
    const float* bias  = (const float*)d_in[3];
    float* out = (float*)d_out;

    static bool attr_set = false;
    if (!attr_set) {
        cudaFuncSetAttribute(qlin, cudaFuncAttributeMaxDynamicSharedMemorySize, SMEM_TOTAL);
        attr_set = true;
    }

    prep_x<<<((IOD / 16) * 4 * 32 + 255) / 256, 256>>>(x);
    qlin<<<32 * KSPLIT, 256, SMEM_TOTAL>>>(wgt, alpha);
    reduce_k<<<((BDIM * IOD / 4) + 255) / 256, 256>>>(bias, out);
}

// round 7
// speedup vs baseline: 1.4619x; 1.4619x over previous
#include <cuda_runtime.h>
#include <cuda_fp16.h>
#include <cstdint>

#define BDIM   64
#define IOD    8192
#define OTILE  64
#define KC     64
#define KSPLIT 2
#define KHALF  (IOD / KSPLIT)      // 4096
#define NITER  (KHALF / KC)        // 64
#define STAGE_BYTES (2 * 8192)     // W(8KB fp16 ternary) + X(8KB fp16)

// scratch (no cudaMalloc allowed)
__device__ __half g_xh[BDIM * IOD];            // x in fp16 (single pass)
__device__ float g_part[KSPLIT][BDIM * IOD];   // split-K partials (alpha applied, no bias)

__global__ void prep_x(const float* __restrict__ x) {
    int i = blockIdx.x * blockDim.x + threadIdx.x;   // float4 index
    if (i < (BDIM * IOD) / 4) {
        float4 v = reinterpret_cast<const float4*>(x)[i];
        __half2 h01, h23;
        h01.x = __float2half_rn(v.x);
        h01.y = __float2half_rn(v.y);
        h23.x = __float2half_rn(v.z);
        h23.y = __float2half_rn(v.w);
        reinterpret_cast<__half2*>(g_xh)[i * 2]     = h01;
        reinterpret_cast<__half2*>(g_xh)[i * 2 + 1] = h23;
    }
}

// 128B-row XOR swizzle (Swizzle<3,4,3>) — conflict-free STS + ldmatrix
__device__ __forceinline__ uint32_t swz(uint32_t off) {
    return off ^ ((off >> 3) & 0x70);
}

__device__ __forceinline__ void ldm_x4(uint32_t& r0, uint32_t& r1,
                                       uint32_t& r2, uint32_t& r3, uint32_t addr) {
    asm volatile("ldmatrix.sync.aligned.m8n8.x4.shared.b16 {%0,%1,%2,%3}, [%4];"
                 : "=r"(r0), "=r"(r1), "=r"(r2), "=r"(r3) : "r"(addr));
}

__device__ __forceinline__ void mma_f16(float* c,
                                        uint32_t a0, uint32_t a1, uint32_t a2, uint32_t a3,
                                        uint32_t b0, uint32_t b1) {
    asm volatile("mma.sync.aligned.m16n8k16.row.col.f32.f16.f16.f32 "
                 "{%0,%1,%2,%3}, {%4,%5,%6,%7}, {%8,%9}, {%0,%1,%2,%3};"
                 : "+f"(c[0]), "+f"(c[1]), "+f"(c[2]), "+f"(c[3])
                 : "r"(a0), "r"(a1), "r"(a2), "r"(a3), "r"(b0), "r"(b1));
}

// ternary quantize one fp32 -> fp16 {-1, 0, +1} bit pattern (alpha applied in epilogue)
__device__ __forceinline__ uint32_t quant1(float f, float thr) {
    uint32_t u = __float_as_uint(f);
    return (fabsf(f) > thr) ? (0x3C00u | ((u >> 16) & 0x8000u)) : 0u;
}

__device__ __forceinline__ void load_tile(const float* __restrict__ wgt,
                                          int n0, int wr, int wc, int xm, int xc, int kbase,
                                          uint4 wreg[4], uint4 xh[2]) {
#pragma unroll
    for (int p = 0; p < 4; ++p)
        wreg[p] = *reinterpret_cast<const uint4*>(
            wgt + (size_t)(n0 + wr + 16 * p) * IOD + kbase + wc * 4);
#pragma unroll
    for (int c2 = 0; c2 < 2; ++c2) {
        int c = xc + 4 * c2;
        xh[c2] = *reinterpret_cast<const uint4*>(&g_xh[(size_t)xm * IOD + kbase + c * 8]);
    }
}

__device__ __forceinline__ void store_tile(unsigned char* smem, int stage,
                                           int wr, int wc, int xm, int xc,
                                           const float thr[4],
                                           const uint4 wreg[4], const uint4 xh[2]) {
    unsigned char* base = smem + stage * STAGE_BYTES;
#pragma unroll
    for (int p = 0; p < 4; ++p) {
        uint32_t q0 = quant1(__uint_as_float(wreg[p].x), thr[p]);
        uint32_t q1 = quant1(__uint_as_float(wreg[p].y), thr[p]);
        uint32_t q2 = quant1(__uint_as_float(wreg[p].z), thr[p]);
        uint32_t q3 = quant1(__uint_as_float(wreg[p].w), thr[p]);
        uint2 v;
        v.x = q0 | (q1 << 16);
        v.y = q2 | (q3 << 16);
        *reinterpret_cast<uint2*>(base + swz((wr + 16 * p) * 128 + wc * 8)) = v;
    }
#pragma unroll
    for (int c2 = 0; c2 < 2; ++c2) {
        int c = xc + 4 * c2;
        uint32_t off = swz(xm * 128 + c * 16);
        *reinterpret_cast<uint4*>(base + 8192 + off) = xh[c2];
    }
}

__device__ __forceinline__ void mma_stage(uint32_t smem_base, int stage,
                                          int m_base, int n_base, int lrow, int lk16,
                                          float acc[2][2][4]) {
    uint32_t wb = smem_base + stage * STAGE_BYTES;
#pragma unroll
    for (int ks = 0; ks < 4; ++ks) {
        int kb = ks * 32 + lk16;
        uint32_t b0, b1, b2, b3;
        ldm_x4(b0, b1, b2, b3, wb + swz((n_base + lrow) * 128 + kb));
        uint32_t ah[2][4];
#pragma unroll
        for (int mt = 0; mt < 2; ++mt) {
            uint32_t roff = swz((m_base + mt * 16 + lrow) * 128 + kb);
            ldm_x4(ah[mt][0], ah[mt][1], ah[mt][2], ah[mt][3], wb + 8192 + roff);
        }
#pragma unroll
        for (int mt = 0; mt < 2; ++mt) {
            mma_f16(acc[mt][0], ah[mt][0], ah[mt][1], ah[mt][2], ah[mt][3], b0, b2);
            mma_f16(acc[mt][1], ah[mt][0], ah[mt][1], ah[mt][2], ah[mt][3], b1, b3);
        }
    }
}

__global__ __launch_bounds__(256, 2) void qlin(
    const float* __restrict__ wgt,
    const float* __restrict__ alpha)
{
    __shared__ __align__(1024) unsigned char smem[2 * STAGE_BYTES];  // 32KB

    const int otile  = blockIdx.x & 127;
    const int khalf  = blockIdx.x >> 7;
    const int n0     = otile * OTILE;
    const int k0     = khalf * KHALF;

    const int tid  = threadIdx.x;
    const int lane = tid & 31;
    const int warp = tid >> 5;
    const int m_base = (warp >> 2) * 32;   // 2 warp rows (M)
    const int n_base = (warp & 3) * 16;    // 4 warp cols (N)

    const uint32_t smem_base = (uint32_t)__cvta_generic_to_shared(smem);

    // weight loader mapping: 16 threads per O-row, 16 rows per pass, 4 passes
    const int wr = tid >> 4;
    const int wc = tid & 15;
    float thr[4];
#pragma unroll
    for (int p = 0; p < 4; ++p)
        thr[p] = 0.5f * (alpha[n0 + wr + 16 * p] + 1e-8f);

    // x loader mapping: 4 threads per batch row
    const int xm = tid >> 2;
    const int xc = tid & 3;

    float acc[2][2][4];
#pragma unroll
    for (int i = 0; i < 2; ++i)
#pragma unroll
        for (int j = 0; j < 2; ++j)
#pragma unroll
            for (int k = 0; k < 4; ++k) acc[i][j][k] = 0.0f;

    const int lrow = lane & 15;
    const int lk16 = (lane >> 4) * 16;

    uint4 wreg[4], xh[2];

    // prologue: fill stage 0
    load_tile(wgt, n0, wr, wc, xm, xc, k0, wreg, xh);
    store_tile(smem, 0, wr, wc, xm, xc, thr, wreg, xh);
    __syncthreads();

    for (int it = 0; it < NITER; ++it) {
        const int cur = it & 1;
        if (it + 1 < NITER)
            load_tile(wgt, n0, wr, wc, xm, xc, k0 + (it + 1) * KC, wreg, xh);

        mma_stage(smem_base, cur, m_base, n_base, lrow, lk16, acc);

        if (it + 1 < NITER)
            store_tile(smem, cur ^ 1, wr, wc, xm, xc, thr, wreg, xh);
        __syncthreads();
    }

    // epilogue: partial[b,o] = alpha[o] * acc   (bias added in reduce)
    float* part = g_part[khalf];
#pragma unroll
    for (int mt = 0; mt < 2; ++mt) {
#pragma unroll
        for (int nt = 0; nt < 2; ++nt) {
            int brow = m_base + mt * 16 + (lane >> 2);
            int o0   = n0 + n_base + nt * 8 + (lane & 3) * 2;
            float2 a2 = *reinterpret_cast<const float2*>(alpha + o0);
            float2 v0, v1;
            v0.x = acc[mt][nt][0] * a2.x;
            v0.y = acc[mt][nt][1] * a2.y;
            v1.x = acc[mt][nt][2] * a2.x;
            v1.y = acc[mt][nt][3] * a2.y;
            *reinterpret_cast<float2*>(part + (size_t)brow * IOD + o0)       = v0;
            *reinterpret_cast<float2*>(part + (size_t)(brow + 8) * IOD + o0) = v1;
        }
    }
}

__global__ void reduce_k(const float* __restrict__ bias, float* __restrict__ out) {
    int i = blockIdx.x * blockDim.x + threadIdx.x;     // float4 index
    if (i < (BDIM * IOD) / 4) {
        float4 p0 = reinterpret_cast<const float4*>(g_part[0])[i];
        float4 p1 = reinterpret_cast<const float4*>(g_part[1])[i];
        int o = (i * 4) & (IOD - 1);
        float4 b = *reinterpret_cast<const float4*>(bias + o);
        float4 r;
        r.x = p0.x + p1.x + b.x;
        r.y = p0.y + p1.y + b.y;
        r.z = p0.z + p1.z + b.z;
        r.w = p0.w + p1.w + b.w;
        reinterpret_cast<float4*>(out)[i] = r;
    }
}

extern "C" void kernel_launch(void* const* d_in, const int* in_sizes, int n_in,
                              void* d_out, int out_size) {
    const float* x     = (const float*)d_in[0];
    const float* wgt   = (const float*)d_in[1];
    const float* alpha = (const float*)d_in[2];
    const float* bias  = (const float*)d_in[3];
    float* out = (float*)d_out;

    prep_x<<<((BDIM * IOD / 4) + 255) / 256, 256>>>(x);
    qlin<<<(IOD / OTILE) * KSPLIT, 256>>>(wgt, alpha);
    reduce_k<<<((BDIM * IOD / 4) + 255) / 256, 256>>>(bias, out);
}